// round 1
// baseline (speedup 1.0000x reference)
#include <cuda_runtime.h>
#include <cuda_bf16.h>

// Problem dims (fixed)
constexpr int Bc = 256;   // batch
constexpr int Cc = 128;   // channels (independent MLPs)
constexpr int Hc = 1024;  // hidden
constexpr int Ic = 512;   // input features
constexpr int Oc = 128;   // output features

// Scratch for the hidden activations: [b][c][h], 128 MB, static device global
// (allocation-guard-safe).
__device__ float g_h[(size_t)Bc * Cc * Hc];

// ---------------------------------------------------------------------------
// Kernel 1: per c,  h[b, c, :] = relu(X_c @ W1_c^T + b1_c)
//   A[m, k] = x[(m*Cc + c)*Ic + k]           (M=256, K=512, k contiguous)
//   B[n, k] = w1[(c*Hc + n)*Ic + k]          (N=1024, k contiguous)
//   store   g_h[(m*Cc + c)*Hc + n]
// Block tile 128(M) x 128(N), K-step 8, 256 threads, 8x8 micro-tile.
// ---------------------------------------------------------------------------
__global__ __launch_bounds__(256, 2)
void mlp_k1(const float* __restrict__ x, const float* __restrict__ w1,
            const float* __restrict__ b1) {
    const int c  = blockIdx.z;
    const int m0 = blockIdx.y * 128;
    const int n0 = blockIdx.x * 128;

    __shared__ float As[8][128];
    __shared__ float Bs[8][128];

    const int tid = threadIdx.x;
    const int tx  = tid & 15;          // 0..15  -> N direction
    const int ty  = tid >> 4;          // 0..15  -> M direction
    const int lr  = tid >> 1;          // 0..127 load row
    const int lk  = (tid & 1) * 4;     // 0 or 4 load k offset

    const float* Ap = x  + ((size_t)(m0 + lr) * Cc + c) * Ic + lk;
    const float* Bp = w1 + ((size_t)c * Hc + (n0 + lr)) * Ic + lk;

    float acc[8][8];
    #pragma unroll
    for (int i = 0; i < 8; i++)
        #pragma unroll
        for (int j = 0; j < 8; j++) acc[i][j] = 0.f;

    for (int k0 = 0; k0 < Ic; k0 += 8) {
        const float4 av = *(const float4*)(Ap + k0);
        const float4 bv = *(const float4*)(Bp + k0);
        __syncthreads();
        As[lk + 0][lr] = av.x; As[lk + 1][lr] = av.y;
        As[lk + 2][lr] = av.z; As[lk + 3][lr] = av.w;
        Bs[lk + 0][lr] = bv.x; Bs[lk + 1][lr] = bv.y;
        Bs[lk + 2][lr] = bv.z; Bs[lk + 3][lr] = bv.w;
        __syncthreads();

        #pragma unroll
        for (int kk = 0; kk < 8; kk++) {
            const float4 a0 = *(const float4*)&As[kk][ty * 8];
            const float4 a1 = *(const float4*)&As[kk][ty * 8 + 4];
            const float4 c0 = *(const float4*)&Bs[kk][tx * 8];
            const float4 c1 = *(const float4*)&Bs[kk][tx * 8 + 4];
            const float a[8] = {a0.x, a0.y, a0.z, a0.w, a1.x, a1.y, a1.z, a1.w};
            const float b[8] = {c0.x, c0.y, c0.z, c0.w, c1.x, c1.y, c1.z, c1.w};
            #pragma unroll
            for (int i = 0; i < 8; i++)
                #pragma unroll
                for (int j = 0; j < 8; j++)
                    acc[i][j] = fmaf(a[i], b[j], acc[i][j]);
        }
    }

    #pragma unroll
    for (int i = 0; i < 8; i++) {
        const int m = m0 + ty * 8 + i;
        float* orow = &g_h[((size_t)m * Cc + c) * Hc + n0 + tx * 8];
        #pragma unroll
        for (int j = 0; j < 8; j++) {
            const int n = n0 + tx * 8 + j;
            const float v = acc[i][j] + __ldg(&b1[c * Hc + n]);
            orow[j] = fmaxf(v, 0.f);
        }
    }
}

// ---------------------------------------------------------------------------
// Kernel 2: per c,  logit[b, c, :] = h[b, c, :] @ W2_c^T + b2_c
//   A[m, k] = g_h[(m*Cc + c)*Hc + k]         (M=256, K=1024, k contiguous)
//   B[n, k] = w2[(c*Oc + n)*Hc + k]          (N=128, k contiguous)
//   store   out[(m*Oc + n)*Cc + c]           (transposed output (B, O, C))
// ---------------------------------------------------------------------------
__global__ __launch_bounds__(256, 2)
void mlp_k2(const float* __restrict__ w2, const float* __restrict__ b2,
            float* __restrict__ out) {
    const int c  = blockIdx.z;
    const int m0 = blockIdx.y * 128;
    const int n0 = blockIdx.x * 128;   // always 0 (Oc == 128)

    __shared__ float As[8][128];
    __shared__ float Bs[8][128];

    const int tid = threadIdx.x;
    const int tx  = tid & 15;
    const int ty  = tid >> 4;
    const int lr  = tid >> 1;
    const int lk  = (tid & 1) * 4;

    const float* Ap = g_h + ((size_t)(m0 + lr) * Cc + c) * Hc + lk;
    const float* Bp = w2  + ((size_t)c * Oc + (n0 + lr)) * Hc + lk;

    float acc[8][8];
    #pragma unroll
    for (int i = 0; i < 8; i++)
        #pragma unroll
        for (int j = 0; j < 8; j++) acc[i][j] = 0.f;

    for (int k0 = 0; k0 < Hc; k0 += 8) {
        const float4 av = *(const float4*)(Ap + k0);
        const float4 bv = *(const float4*)(Bp + k0);
        __syncthreads();
        As[lk + 0][lr] = av.x; As[lk + 1][lr] = av.y;
        As[lk + 2][lr] = av.z; As[lk + 3][lr] = av.w;
        Bs[lk + 0][lr] = bv.x; Bs[lk + 1][lr] = bv.y;
        Bs[lk + 2][lr] = bv.z; Bs[lk + 3][lr] = bv.w;
        __syncthreads();

        #pragma unroll
        for (int kk = 0; kk < 8; kk++) {
            const float4 a0 = *(const float4*)&As[kk][ty * 8];
            const float4 a1 = *(const float4*)&As[kk][ty * 8 + 4];
            const float4 c0 = *(const float4*)&Bs[kk][tx * 8];
            const float4 c1 = *(const float4*)&Bs[kk][tx * 8 + 4];
            const float a[8] = {a0.x, a0.y, a0.z, a0.w, a1.x, a1.y, a1.z, a1.w};
            const float b[8] = {c0.x, c0.y, c0.z, c0.w, c1.x, c1.y, c1.z, c1.w};
            #pragma unroll
            for (int i = 0; i < 8; i++)
                #pragma unroll
                for (int j = 0; j < 8; j++)
                    acc[i][j] = fmaf(a[i], b[j], acc[i][j]);
        }
    }

    #pragma unroll
    for (int i = 0; i < 8; i++) {
        const int m = m0 + ty * 8 + i;
        #pragma unroll
        for (int j = 0; j < 8; j++) {
            const int n = n0 + tx * 8 + j;
            const float v = acc[i][j] + __ldg(&b2[c * Oc + n]);
            out[((size_t)m * Oc + n) * Cc + c] = v;   // (B, O, C) layout
        }
    }
}

extern "C" void kernel_launch(void* const* d_in, const int* in_sizes, int n_in,
                              void* d_out, int out_size) {
    const float* x  = (const float*)d_in[0];
    const float* w1 = (const float*)d_in[1];
    const float* b1 = (const float*)d_in[2];
    const float* w2 = (const float*)d_in[3];
    const float* b2 = (const float*)d_in[4];
    float* out = (float*)d_out;

    dim3 block(256);
    dim3 grid1(Hc / 128, Bc / 128, Cc);   // (8, 2, 128)
    dim3 grid2(Oc / 128, Bc / 128, Cc);   // (1, 2, 128)
    mlp_k1<<<grid1, block>>>(x, w1, b1);
    mlp_k2<<<grid2, block>>>(w2, b2, out);
}

// round 2
// speedup vs baseline: 2.4124x; 2.4124x over previous
#include <cuda_runtime.h>
#include <cstdint>

constexpr int Bc = 256;   // batch
constexpr int Cc = 128;   // channels
constexpr int Hc = 1024;  // hidden
constexpr int Ic = 512;   // input features
constexpr int Oc = 128;   // output features

// hidden activations scratch: [b][c][h]  (128 MB, static device global)
__device__ float g_h[(size_t)Bc * Cc * Hc];

__device__ __forceinline__ uint32_t f2tf(float f) {
    uint32_t u;
    asm("cvt.rna.tf32.f32 %0, %1;" : "=r"(u) : "f"(f));
    return u;
}

__device__ __forceinline__ void mma8(float4& d,
                                     uint32_t a0, uint32_t a1, uint32_t a2, uint32_t a3,
                                     uint32_t b0, uint32_t b1) {
    asm volatile(
        "mma.sync.aligned.m16n8k8.row.col.f32.tf32.tf32.f32 "
        "{%0,%1,%2,%3}, {%4,%5,%6,%7}, {%8,%9}, {%0,%1,%2,%3};"
        : "+f"(d.x), "+f"(d.y), "+f"(d.z), "+f"(d.w)
        : "r"(a0), "r"(a1), "r"(a2), "r"(a3), "r"(b0), "r"(b1));
}

// Shared GEMM mainloop over one 128x128 block tile, K-step 16.
// A: [M rows][K] k-contiguous rows at stride lda; B: [N rows][K] at stride ldb.
// Smem rows padded to 20 words -> conflict-free tf32 fragment loads.
#define GEMM_MAINLOOP(KDIM, AG, BG)                                              \
    float4 acc[4][4];                                                            \
    _Pragma("unroll") for (int t = 0; t < 4; t++)                                \
        _Pragma("unroll") for (int u = 0; u < 4; u++)                            \
            acc[t][u] = make_float4(0.f, 0.f, 0.f, 0.f);                         \
    float4 ar0 = *(const float4*)(AG);                                           \
    float4 ar1 = *(const float4*)(AG + 4);                                       \
    float4 br0 = *(const float4*)(BG);                                           \
    float4 br1 = *(const float4*)(BG + 4);                                       \
    for (int k0 = 0; k0 < (KDIM); k0 += 16) {                                    \
        __syncthreads();                                                         \
        {                                                                        \
            uint4 v0 = {f2tf(ar0.x), f2tf(ar0.y), f2tf(ar0.z), f2tf(ar0.w)};     \
            uint4 v1 = {f2tf(ar1.x), f2tf(ar1.y), f2tf(ar1.z), f2tf(ar1.w)};     \
            uint4 w0 = {f2tf(br0.x), f2tf(br0.y), f2tf(br0.z), f2tf(br0.w)};     \
            uint4 w1 = {f2tf(br1.x), f2tf(br1.y), f2tf(br1.z), f2tf(br1.w)};     \
            *(uint4*)(Asw)     = v0;                                             \
            *(uint4*)(Asw + 4) = v1;                                             \
            *(uint4*)(Bsw)     = w0;                                             \
            *(uint4*)(Bsw + 4) = w1;                                             \
        }                                                                        \
        __syncthreads();                                                         \
        if (k0 + 16 < (KDIM)) {                                                  \
            ar0 = *(const float4*)(AG + k0 + 16);                                \
            ar1 = *(const float4*)(AG + k0 + 20);                                \
            br0 = *(const float4*)(BG + k0 + 16);                                \
            br1 = *(const float4*)(BG + k0 + 20);                                \
        }                                                                        \
        _Pragma("unroll") for (int kk = 0; kk < 16; kk += 8) {                   \
            uint32_t a[4][4], b[4][2];                                           \
            _Pragma("unroll") for (int t = 0; t < 4; t++) {                      \
                a[t][0] = Af[(t * 16) * 20 + kk];                                \
                a[t][1] = Af[(t * 16 + 8) * 20 + kk];                            \
                a[t][2] = Af[(t * 16) * 20 + kk + 4];                            \
                a[t][3] = Af[(t * 16 + 8) * 20 + kk + 4];                        \
            }                                                                    \
            _Pragma("unroll") for (int u = 0; u < 4; u++) {                      \
                b[u][0] = Bf[(u * 8) * 20 + kk];                                 \
                b[u][1] = Bf[(u * 8) * 20 + kk + 4];                             \
            }                                                                    \
            _Pragma("unroll") for (int t = 0; t < 4; t++)                        \
                _Pragma("unroll") for (int u = 0; u < 4; u++)                    \
                    mma8(acc[t][u], a[t][0], a[t][1], a[t][2], a[t][3],          \
                         b[u][0], b[u][1]);                                      \
        }                                                                        \
    }

// ---------------------------------------------------------------------------
// Kernel 1: h[b, c, :] = relu(X_c @ W1_c^T + b1_c)
// ---------------------------------------------------------------------------
__global__ __launch_bounds__(256, 2)
void mlp_k1(const float* __restrict__ x, const float* __restrict__ w1,
            const float* __restrict__ b1) {
    const int c = blockIdx.z, m0 = blockIdx.y * 128, n0 = blockIdx.x * 128;
    __shared__ uint32_t As[128 * 20];
    __shared__ uint32_t Bs[128 * 20];

    const int tid = threadIdx.x, l = tid & 31, w = tid >> 5;
    const int wm = (w & 1) * 64, wn = (w >> 1) * 32;
    const int lr4 = l >> 2, lc4 = l & 3;
    const int row = tid >> 1, koff = (tid & 1) * 8;

    const float* AG = x  + ((size_t)(m0 + row) * Cc + c) * Ic + koff;
    const float* BG = w1 + ((size_t)c * Hc + n0 + row) * Ic + koff;

    uint32_t* Asw = As + row * 20 + koff;
    uint32_t* Bsw = Bs + row * 20 + koff;
    const uint32_t* Af = As + (wm + lr4) * 20 + lc4;
    const uint32_t* Bf = Bs + (wn + lr4) * 20 + lc4;

    GEMM_MAINLOOP(Ic, AG, BG)

    #pragma unroll
    for (int t = 0; t < 4; t++) {
        const int r0 = m0 + wm + t * 16 + lr4;
        #pragma unroll
        for (int u = 0; u < 4; u++) {
            const int n = n0 + wn + u * 8 + lc4 * 2;
            const float2 bb = *(const float2*)&b1[c * Hc + n];
            float2 lo = {fmaxf(acc[t][u].x + bb.x, 0.f),
                         fmaxf(acc[t][u].y + bb.y, 0.f)};
            float2 hi = {fmaxf(acc[t][u].z + bb.x, 0.f),
                         fmaxf(acc[t][u].w + bb.y, 0.f)};
            *(float2*)&g_h[((size_t)r0 * Cc + c) * Hc + n]       = lo;
            *(float2*)&g_h[((size_t)(r0 + 8) * Cc + c) * Hc + n] = hi;
        }
    }
}

// ---------------------------------------------------------------------------
// Kernel 2: out[b, :, c] = h[b, c, :] @ W2_c^T + b2_c   (output (B, O, C))
// ---------------------------------------------------------------------------
__global__ __launch_bounds__(256, 2)
void mlp_k2(const float* __restrict__ w2, const float* __restrict__ b2,
            float* __restrict__ out) {
    const int c = blockIdx.z, m0 = blockIdx.y * 128, n0 = 0;
    __shared__ uint32_t As[128 * 20];
    __shared__ uint32_t Bs[128 * 20];

    const int tid = threadIdx.x, l = tid & 31, w = tid >> 5;
    const int wm = (w & 1) * 64, wn = (w >> 1) * 32;
    const int lr4 = l >> 2, lc4 = l & 3;
    const int row = tid >> 1, koff = (tid & 1) * 8;

    const float* AG = g_h + ((size_t)(m0 + row) * Cc + c) * Hc + koff;
    const float* BG = w2  + ((size_t)c * Oc + n0 + row) * Hc + koff;

    uint32_t* Asw = As + row * 20 + koff;
    uint32_t* Bsw = Bs + row * 20 + koff;
    const uint32_t* Af = As + (wm + lr4) * 20 + lc4;
    const uint32_t* Bf = Bs + (wn + lr4) * 20 + lc4;

    GEMM_MAINLOOP(Hc, AG, BG)

    #pragma unroll
    for (int t = 0; t < 4; t++) {
        const int r0 = m0 + wm + t * 16 + lr4;
        #pragma unroll
        for (int u = 0; u < 4; u++) {
            const int n = n0 + wn + u * 8 + lc4 * 2;
            const float2 bb = *(const float2*)&b2[c * Oc + n];
            out[((size_t)r0 * Oc + n) * Cc + c]           = acc[t][u].x + bb.x;
            out[((size_t)r0 * Oc + n + 1) * Cc + c]       = acc[t][u].y + bb.y;
            out[((size_t)(r0 + 8) * Oc + n) * Cc + c]     = acc[t][u].z + bb.x;
            out[((size_t)(r0 + 8) * Oc + n + 1) * Cc + c] = acc[t][u].w + bb.y;
        }
    }
}

extern "C" void kernel_launch(void* const* d_in, const int* in_sizes, int n_in,
                              void* d_out, int out_size) {
    const float* x  = (const float*)d_in[0];
    const float* w1 = (const float*)d_in[1];
    const float* b1 = (const float*)d_in[2];
    const float* w2 = (const float*)d_in[3];
    const float* b2 = (const float*)d_in[4];
    float* out = (float*)d_out;

    dim3 block(256);
    dim3 grid1(Hc / 128, Bc / 128, Cc);   // (8, 2, 128)
    dim3 grid2(1,        Bc / 128, Cc);   // (1, 2, 128)
    mlp_k1<<<grid1, block>>>(x, w1, b1);
    mlp_k2<<<grid2, block>>>(w2, b2, out);
}

// round 3
// speedup vs baseline: 2.5509x; 1.0574x over previous
#include <cuda_runtime.h>
#include <cstdint>

constexpr int Bc = 256;   // batch
constexpr int Cc = 128;   // channels
constexpr int Hc = 1024;  // hidden
constexpr int Ic = 512;   // input features
constexpr int Oc = 128;   // output features

constexpr int BUFSZ = 128 * 20;   // one 128-row x (16+4 pad) word tile

// hidden activations scratch: [b][c][h]  (128 MB, static device global)
__device__ float g_h[(size_t)Bc * Cc * Hc];

__device__ __forceinline__ uint32_t f2tf(float f) {
    uint32_t u;
    asm("cvt.rna.tf32.f32 %0, %1;" : "=r"(u) : "f"(f));
    return u;
}

__device__ __forceinline__ void mma8(float4& d,
                                     uint32_t a0, uint32_t a1, uint32_t a2, uint32_t a3,
                                     uint32_t b0, uint32_t b1) {
    asm volatile(
        "mma.sync.aligned.m16n8k8.row.col.f32.tf32.tf32.f32 "
        "{%0,%1,%2,%3}, {%4,%5,%6,%7}, {%8,%9}, {%0,%1,%2,%3};"
        : "+f"(d.x), "+f"(d.y), "+f"(d.z), "+f"(d.w)
        : "r"(a0), "r"(a1), "r"(a2), "r"(a3), "r"(b0), "r"(b1));
}

// Double-buffered GEMM mainloop, 128x128 block tile, K-step 16.
// One __syncthreads per K-step; buffer reuse distance = 2 iters (safe).
// Smem rows padded to 20 words -> conflict-free tf32 fragment LDS.
#define GEMM_MAINLOOP(KDIM, AG, BG)                                              \
    float4 acc[4][4];                                                            \
    _Pragma("unroll") for (int t = 0; t < 4; t++)                                \
        _Pragma("unroll") for (int u = 0; u < 4; u++)                            \
            acc[t][u] = make_float4(0.f, 0.f, 0.f, 0.f);                         \
    float4 ar0 = *(const float4*)(AG);                                           \
    float4 ar1 = *(const float4*)(AG + 4);                                       \
    float4 br0 = *(const float4*)(BG);                                           \
    float4 br1 = *(const float4*)(BG + 4);                                       \
    int p = 0;                                                                   \
    for (int k0 = 0; k0 < (KDIM); k0 += 16) {                                    \
        {                                                                        \
            uint32_t* Aw = As + p * BUFSZ + swoff;                               \
            uint32_t* Bw = Bs + p * BUFSZ + swoff;                               \
            uint4 v0 = {f2tf(ar0.x), f2tf(ar0.y), f2tf(ar0.z), f2tf(ar0.w)};     \
            uint4 v1 = {f2tf(ar1.x), f2tf(ar1.y), f2tf(ar1.z), f2tf(ar1.w)};     \
            uint4 w0 = {f2tf(br0.x), f2tf(br0.y), f2tf(br0.z), f2tf(br0.w)};     \
            uint4 w1 = {f2tf(br1.x), f2tf(br1.y), f2tf(br1.z), f2tf(br1.w)};     \
            *(uint4*)(Aw)     = v0;                                              \
            *(uint4*)(Aw + 4) = v1;                                              \
            *(uint4*)(Bw)     = w0;                                              \
            *(uint4*)(Bw + 4) = w1;                                              \
        }                                                                        \
        __syncthreads();                                                         \
        if (k0 + 16 < (KDIM)) {                                                  \
            ar0 = *(const float4*)(AG + k0 + 16);                                \
            ar1 = *(const float4*)(AG + k0 + 20);                                \
            br0 = *(const float4*)(BG + k0 + 16);                                \
            br1 = *(const float4*)(BG + k0 + 20);                                \
        }                                                                        \
        {                                                                        \
            const uint32_t* Afp = As + p * BUFSZ + faoff;                        \
            const uint32_t* Bfp = Bs + p * BUFSZ + fboff;                        \
            _Pragma("unroll") for (int kk = 0; kk < 16; kk += 8) {               \
                uint32_t a[4][4], b[4][2];                                       \
                _Pragma("unroll") for (int t = 0; t < 4; t++) {                  \
                    a[t][0] = Afp[(t * 16) * 20 + kk];                           \
                    a[t][1] = Afp[(t * 16 + 8) * 20 + kk];                       \
                    a[t][2] = Afp[(t * 16) * 20 + kk + 4];                       \
                    a[t][3] = Afp[(t * 16 + 8) * 20 + kk + 4];                   \
                }                                                                \
                _Pragma("unroll") for (int u = 0; u < 4; u++) {                  \
                    b[u][0] = Bfp[(u * 8) * 20 + kk];                            \
                    b[u][1] = Bfp[(u * 8) * 20 + kk + 4];                        \
                }                                                                \
                _Pragma("unroll") for (int t = 0; t < 4; t++)                    \
                    _Pragma("unroll") for (int u = 0; u < 4; u++)                \
                        mma8(acc[t][u], a[t][0], a[t][1], a[t][2], a[t][3],      \
                             b[u][0], b[u][1]);                                  \
            }                                                                    \
        }                                                                        \
        p ^= 1;                                                                  \
    }

// ---------------------------------------------------------------------------
// Kernel 1: h[b, c, :] = relu(X_c @ W1_c^T + b1_c)
// ---------------------------------------------------------------------------
__global__ __launch_bounds__(256, 2)
void mlp_k1(const float* __restrict__ x, const float* __restrict__ w1,
            const float* __restrict__ b1) {
    const int c = blockIdx.z, m0 = blockIdx.y * 128, n0 = blockIdx.x * 128;
    __shared__ uint32_t As[2 * BUFSZ];
    __shared__ uint32_t Bs[2 * BUFSZ];

    const int tid = threadIdx.x, l = tid & 31, w = tid >> 5;
    const int wm = (w & 1) * 64, wn = (w >> 1) * 32;
    const int lr4 = l >> 2, lc4 = l & 3;
    const int row = tid >> 1, koff = (tid & 1) * 8;

    const float* AG = x  + ((size_t)(m0 + row) * Cc + c) * Ic + koff;
    const float* BG = w1 + ((size_t)c * Hc + n0 + row) * Ic + koff;

    const int swoff = row * 20 + koff;
    const int faoff = (wm + lr4) * 20 + lc4;
    const int fboff = (wn + lr4) * 20 + lc4;

    GEMM_MAINLOOP(Ic, AG, BG)

    #pragma unroll
    for (int t = 0; t < 4; t++) {
        const int r0 = m0 + wm + t * 16 + lr4;
        #pragma unroll
        for (int u = 0; u < 4; u++) {
            const int n = n0 + wn + u * 8 + lc4 * 2;
            const float2 bb = *(const float2*)&b1[c * Hc + n];
            float2 lo = {fmaxf(acc[t][u].x + bb.x, 0.f),
                         fmaxf(acc[t][u].y + bb.y, 0.f)};
            float2 hi = {fmaxf(acc[t][u].z + bb.x, 0.f),
                         fmaxf(acc[t][u].w + bb.y, 0.f)};
            *(float2*)&g_h[((size_t)r0 * Cc + c) * Hc + n]       = lo;
            *(float2*)&g_h[((size_t)(r0 + 8) * Cc + c) * Hc + n] = hi;
        }
    }
}

// ---------------------------------------------------------------------------
// Kernel 2: out[b, :, c] = h[b, c, :] @ W2_c^T + b2_c   (output (B, O, C))
// ---------------------------------------------------------------------------
__global__ __launch_bounds__(256, 2)
void mlp_k2(const float* __restrict__ w2, const float* __restrict__ b2,
            float* __restrict__ out) {
    const int c = blockIdx.z, m0 = blockIdx.y * 128, n0 = 0;
    __shared__ uint32_t As[2 * BUFSZ];
    __shared__ uint32_t Bs[2 * BUFSZ];

    const int tid = threadIdx.x, l = tid & 31, w = tid >> 5;
    const int wm = (w & 1) * 64, wn = (w >> 1) * 32;
    const int lr4 = l >> 2, lc4 = l & 3;
    const int row = tid >> 1, koff = (tid & 1) * 8;

    const float* AG = g_h + ((size_t)(m0 + row) * Cc + c) * Hc + koff;
    const float* BG = w2  + ((size_t)c * Oc + n0 + row) * Hc + koff;

    const int swoff = row * 20 + koff;
    const int faoff = (wm + lr4) * 20 + lc4;
    const int fboff = (wn + lr4) * 20 + lc4;

    GEMM_MAINLOOP(Hc, AG, BG)

    #pragma unroll
    for (int t = 0; t < 4; t++) {
        const int r0 = m0 + wm + t * 16 + lr4;
        #pragma unroll
        for (int u = 0; u < 4; u++) {
            const int n = n0 + wn + u * 8 + lc4 * 2;
            const float2 bb = *(const float2*)&b2[c * Oc + n];
            out[((size_t)r0 * Oc + n) * Cc + c]           = acc[t][u].x + bb.x;
            out[((size_t)r0 * Oc + n + 1) * Cc + c]       = acc[t][u].y + bb.y;
            out[((size_t)(r0 + 8) * Oc + n) * Cc + c]     = acc[t][u].z + bb.x;
            out[((size_t)(r0 + 8) * Oc + n + 1) * Cc + c] = acc[t][u].w + bb.y;
        }
    }
}

extern "C" void kernel_launch(void* const* d_in, const int* in_sizes, int n_in,
                              void* d_out, int out_size) {
    const float* x  = (const float*)d_in[0];
    const float* w1 = (const float*)d_in[1];
    const float* b1 = (const float*)d_in[2];
    const float* w2 = (const float*)d_in[3];
    const float* b2 = (const float*)d_in[4];
    float* out = (float*)d_out;

    dim3 block(256);
    dim3 grid1(Hc / 128, Bc / 128, Cc);   // (8, 2, 128)
    dim3 grid2(1,        Bc / 128, Cc);   // (1, 2, 128)
    mlp_k1<<<grid1, block>>>(x, w1, b1);
    mlp_k2<<<grid2, block>>>(w2, b2, out);
}

// round 6
// speedup vs baseline: 3.0268x; 1.1866x over previous
#include <cuda_runtime.h>
#include <cstdint>

constexpr int Bc = 256;   // batch
constexpr int Cc = 128;   // channels
constexpr int Hc = 1024;  // hidden
constexpr int Ic = 512;   // input features
constexpr int Oc = 128;   // output features

constexpr int STAGES = 4;
constexpr int TILEW  = 128 * 20;        // words per (A or B) stage tile (16 data + 4 pad / row)
constexpr int STAGEW = 2 * TILEW;       // A tile then B tile
constexpr int SMEM_BYTES = STAGES * STAGEW * 4;   // 81920 B

// hidden activations scratch: [b][c][h]  (128 MB, static device global)
__device__ float g_h[(size_t)Bc * Cc * Hc];

__device__ __forceinline__ uint32_t s2u(const void* p) {
    uint32_t a;
    asm("{ .reg .u64 t; cvta.to.shared.u64 t, %1; cvt.u32.u64 %0, t; }" : "=r"(a) : "l"(p));
    return a;
}
__device__ __forceinline__ void cp16(uint32_t dst, const float* src) {
    asm volatile("cp.async.cg.shared.global [%0], [%1], 16;" :: "r"(dst), "l"(src));
}
__device__ __forceinline__ void mma8(float4& d,
                                     uint32_t a0, uint32_t a1, uint32_t a2, uint32_t a3,
                                     uint32_t b0, uint32_t b1) {
    asm volatile(
        "mma.sync.aligned.m16n8k8.row.col.f32.tf32.tf32.f32 "
        "{%0,%1,%2,%3}, {%4,%5,%6,%7}, {%8,%9}, {%0,%1,%2,%3};"
        : "+f"(d.x), "+f"(d.y), "+f"(d.z), "+f"(d.w)
        : "r"(a0), "r"(a1), "r"(a2), "r"(a3), "r"(b0), "r"(b1));
}
// fp32 bits -> tf32 round-to-nearest: HMMA ignores the low 13 bits, so a
// single +0x1000 (carry propagates into exponent correctly) implements RN.
__device__ __forceinline__ uint32_t rn(uint32_t u) { return u + 0x1000u; }

// ---------------------------------------------------------------------------
// 4-stage cp.async pipelined tf32 GEMM mainloop, 128x128 block tile, K16 step.
// Per thread per stage: 8 floats of A + 8 floats of B (2x cp.async.16B each).
// ---------------------------------------------------------------------------
#define CP_STAGE(S)                                                              \
    do {                                                                         \
        const int _sl = (S) & 3;                                                 \
        const uint32_t _aw = sA + (uint32_t)(_sl * STAGEW) * 4;                  \
        const uint32_t _bw = _aw + TILEW * 4;                                    \
        cp16(_aw,      AGc + (S) * 16);                                          \
        cp16(_aw + 16, AGc + (S) * 16 + 4);                                      \
        cp16(_bw,      BGc + (S) * 16);                                          \
        cp16(_bw + 16, BGc + (S) * 16 + 4);                                      \
    } while (0)

#define GEMM_MAINLOOP(KDIM)                                                      \
    float4 acc[4][4];                                                            \
    _Pragma("unroll") for (int t = 0; t < 4; t++)                                \
        _Pragma("unroll") for (int u = 0; u < 4; u++)                            \
            acc[t][u] = make_float4(0.f, 0.f, 0.f, 0.f);                         \
    const int NIT = (KDIM) / 16;                                                 \
    _Pragma("unroll") for (int s = 0; s < 3; s++) {                              \
        CP_STAGE(s);                                                             \
        asm volatile("cp.async.commit_group;" ::: "memory");                     \
    }                                                                            \
    for (int i = 0; i < NIT; i++) {                                              \
        const int sl = i & 3;                                                    \
        asm volatile("cp.async.wait_group 2;" ::: "memory");                     \
        __syncthreads();                                                         \
        if (i + 3 < NIT) CP_STAGE(i + 3);                                        \
        asm volatile("cp.async.commit_group;" ::: "memory");                     \
        const uint32_t* Afp = smw + sl * STAGEW + faoff;                         \
        const uint32_t* Bfp = smw + sl * STAGEW + TILEW + fboff;                 \
        _Pragma("unroll") for (int kk = 0; kk < 16; kk += 8) {                   \
            uint32_t a[4][4], b[4][2];                                           \
            _Pragma("unroll") for (int t = 0; t < 4; t++) {                      \
                a[t][0] = rn(Afp[(t * 16) * 20 + kk]);                           \
                a[t][1] = rn(Afp[(t * 16 + 8) * 20 + kk]);                       \
                a[t][2] = rn(Afp[(t * 16) * 20 + kk + 4]);                       \
                a[t][3] = rn(Afp[(t * 16 + 8) * 20 + kk + 4]);                   \
            }                                                                    \
            _Pragma("unroll") for (int u = 0; u < 4; u++) {                      \
                b[u][0] = rn(Bfp[(u * 8) * 20 + kk]);                            \
                b[u][1] = rn(Bfp[(u * 8) * 20 + kk + 4]);                        \
            }                                                                    \
            _Pragma("unroll") for (int t = 0; t < 4; t++)                        \
                _Pragma("unroll") for (int u = 0; u < 4; u++)                    \
                    mma8(acc[t][u], a[t][0], a[t][1], a[t][2], a[t][3],          \
                         b[u][0], b[u][1]);                                      \
        }                                                                        \
    }

// ---------------------------------------------------------------------------
// Kernel 1: h[b, c, :] = relu(X_c @ W1_c^T + b1_c)
// ---------------------------------------------------------------------------
__global__ __launch_bounds__(256, 2)
void mlp_k1(const float* __restrict__ x, const float* __restrict__ w1,
            const float* __restrict__ b1) {
    extern __shared__ uint32_t smw[];
    const int c = blockIdx.z, m0 = blockIdx.y * 128, n0 = blockIdx.x * 128;

    const int tid = threadIdx.x, l = tid & 31, w = tid >> 5;
    const int wm = (w & 1) * 64, wn = (w >> 1) * 32;
    const int lr4 = l >> 2, lc4 = l & 3;
    const int row = tid >> 1, koff = (tid & 1) * 8;

    const float* AGc = x  + ((size_t)(m0 + row) * Cc + c) * Ic + koff;
    const float* BGc = w1 + ((size_t)c * Hc + n0 + row) * Ic + koff;
    const uint32_t sA = s2u(smw) + (uint32_t)(row * 20 + koff) * 4;
    const int faoff = (wm + lr4) * 20 + lc4;
    const int fboff = (wn + lr4) * 20 + lc4;

    GEMM_MAINLOOP(Ic)

    #pragma unroll
    for (int t = 0; t < 4; t++) {
        const int r0 = m0 + wm + t * 16 + lr4;
        #pragma unroll
        for (int u = 0; u < 4; u++) {
            const int n = n0 + wn + u * 8 + lc4 * 2;
            const float2 bb = *(const float2*)&b1[c * Hc + n];
            float2 lo = {fmaxf(acc[t][u].x + bb.x, 0.f),
                         fmaxf(acc[t][u].y + bb.y, 0.f)};
            float2 hi = {fmaxf(acc[t][u].z + bb.x, 0.f),
                         fmaxf(acc[t][u].w + bb.y, 0.f)};
            *(float2*)&g_h[((size_t)r0 * Cc + c) * Hc + n]       = lo;
            *(float2*)&g_h[((size_t)(r0 + 8) * Cc + c) * Hc + n] = hi;
        }
    }
}

// ---------------------------------------------------------------------------
// Kernel 2: out[b, :, c] = h[b, c, :] @ W2_c^T + b2_c   (output (B, O, C))
// ---------------------------------------------------------------------------
__global__ __launch_bounds__(256, 2)
void mlp_k2(const float* __restrict__ w2, const float* __restrict__ b2,
            float* __restrict__ out) {
    extern __shared__ uint32_t smw[];
    const int c = blockIdx.z, m0 = blockIdx.y * 128, n0 = 0;

    const int tid = threadIdx.x, l = tid & 31, w = tid >> 5;
    const int wm = (w & 1) * 64, wn = (w >> 1) * 32;
    const int lr4 = l >> 2, lc4 = l & 3;
    const int row = tid >> 1, koff = (tid & 1) * 8;

    const float* AGc = g_h + ((size_t)(m0 + row) * Cc + c) * Hc + koff;
    const float* BGc = w2  + ((size_t)c * Oc + n0 + row) * Hc + koff;
    const uint32_t sA = s2u(smw) + (uint32_t)(row * 20 + koff) * 4;
    const int faoff = (wm + lr4) * 20 + lc4;
    const int fboff = (wn + lr4) * 20 + lc4;

    GEMM_MAINLOOP(Hc)

    #pragma unroll
    for (int t = 0; t < 4; t++) {
        const int r0 = m0 + wm + t * 16 + lr4;
        #pragma unroll
        for (int u = 0; u < 4; u++) {
            const int n = n0 + wn + u * 8 + lc4 * 2;
            const float2 bb = *(const float2*)&b2[c * Oc + n];
            out[((size_t)r0 * Oc + n) * Cc + c]           = acc[t][u].x + bb.x;
            out[((size_t)r0 * Oc + n + 1) * Cc + c]       = acc[t][u].y + bb.y;
            out[((size_t)(r0 + 8) * Oc + n) * Cc + c]     = acc[t][u].z + bb.x;
            out[((size_t)(r0 + 8) * Oc + n + 1) * Cc + c] = acc[t][u].w + bb.y;
        }
    }
}

extern "C" void kernel_launch(void* const* d_in, const int* in_sizes, int n_in,
                              void* d_out, int out_size) {
    const float* x  = (const float*)d_in[0];
    const float* w1 = (const float*)d_in[1];
    const float* b1 = (const float*)d_in[2];
    const float* w2 = (const float*)d_in[3];
    const float* b2 = (const float*)d_in[4];
    float* out = (float*)d_out;

    static bool attr_set = false;
    if (!attr_set) {
        cudaFuncSetAttribute(mlp_k1, cudaFuncAttributeMaxDynamicSharedMemorySize, SMEM_BYTES);
        cudaFuncSetAttribute(mlp_k2, cudaFuncAttributeMaxDynamicSharedMemorySize, SMEM_BYTES);
        attr_set = true;
    }

    dim3 block(256);
    dim3 grid1(Hc / 128, Bc / 128, Cc);   // (8, 2, 128)
    dim3 grid2(1,        Bc / 128, Cc);   // (1, 2, 128)
    mlp_k1<<<grid1, block, SMEM_BYTES>>>(x, w1, b1);
    mlp_k2<<<grid2, block, SMEM_BYTES>>>(w2, b2, out);
}